// round 1
// baseline (speedup 1.0000x reference)
#include <cuda_runtime.h>
#include <math.h>

// EGNN layer, collapsed to the diagonal:
//   h_e[b,i,:] = he[b,i,i,:]  (the eye-mask kills all off-diagonal edges)
// On the diagonal: x_j - x_i = 0 -> norm = sqrt(EPS) (constant),
//                  hi = hj = h[b,i].
// So per row r (r = b*N + n, R = B*N rows total):
//   t1  = silu( h_r @ (We1[0:F] + We1[F:2F]) + sqrt(EPS)*We1[2F] + be1 )
//   t2  = silu( t1 @ We2 + be2 )
//   att = sigmoid( t2 @ Wa + ba )
//   he  = att * t2
//   t3  = silu( h_r @ Wn1[0:F] + he @ Wn1[F:2F] + bn1 )
//   out = t3 @ Wn2 + bn2
// Output buffer: [out (R*32 floats)] then [x passthrough (R*3 floats)].
//
// One warp per row; lane t owns neuron t (F=H=O=32). Dot products via
// __shfl_sync broadcast. Weight reads coalesced & L1/L2-resident.

#define SQRT_EPS 0.0031622776601683794f  // sqrt(1e-5)

__device__ __forceinline__ float silu_f(float v) {
    return v / (1.0f + __expf(-v));
}

__global__ void __launch_bounds__(256)
egnn_diag_kernel(const float* __restrict__ h,
                 const float* __restrict__ x,
                 const float* __restrict__ We1, const float* __restrict__ be1,
                 const float* __restrict__ We2, const float* __restrict__ be2,
                 const float* __restrict__ Wa,  const float* __restrict__ ba,
                 const float* __restrict__ Wn1, const float* __restrict__ bn1,
                 const float* __restrict__ Wn2, const float* __restrict__ bn2,
                 float* __restrict__ out, float* __restrict__ xout, int R)
{
    const int warp = (blockIdx.x * blockDim.x + threadIdx.x) >> 5;
    const int lane = threadIdx.x & 31;
    if (warp >= R) return;

    // Load this row's feature (coalesced: 32 consecutive floats per warp)
    const float hv = h[warp * 32 + lane];

    // ---- edge MLP layer 1: e_in = [h, h, sqrt(EPS)] @ We1 + be1 ----
    float acc = be1[lane] + SQRT_EPS * We1[64 * 32 + lane];
    #pragma unroll
    for (int f = 0; f < 32; ++f) {
        const float hf = __shfl_sync(0xffffffffu, hv, f);
        acc += hf * (We1[f * 32 + lane] + We1[(32 + f) * 32 + lane]);
    }
    const float t1 = silu_f(acc);

    // ---- edge MLP layer 2 ----
    float acc2 = be2[lane];
    #pragma unroll
    for (int f = 0; f < 32; ++f) {
        acc2 += __shfl_sync(0xffffffffu, t1, f) * We2[f * 32 + lane];
    }
    const float t2 = silu_f(acc2);

    // ---- attention gate: sigmoid(t2 @ Wa + ba), scalar per row ----
    float s = t2 * Wa[lane];
    #pragma unroll
    for (int off = 16; off > 0; off >>= 1)
        s += __shfl_xor_sync(0xffffffffu, s, off);
    const float att = 1.0f / (1.0f + __expf(-(s + ba[0])));
    const float he = att * t2;

    // ---- node MLP layer 1: [h, he] @ Wn1 + bn1 ----
    float acc3 = bn1[lane];
    #pragma unroll
    for (int f = 0; f < 32; ++f) {
        const float hf  = __shfl_sync(0xffffffffu, hv, f);
        const float hef = __shfl_sync(0xffffffffu, he, f);
        acc3 += hf * Wn1[f * 32 + lane] + hef * Wn1[(32 + f) * 32 + lane];
    }
    const float t3 = silu_f(acc3);

    // ---- node MLP layer 2 ----
    float acc4 = bn2[lane];
    #pragma unroll
    for (int f = 0; f < 32; ++f) {
        acc4 += __shfl_sync(0xffffffffu, t3, f) * Wn2[f * 32 + lane];
    }

    out[warp * 32 + lane] = acc4;

    // ---- x passthrough (second tuple element) ----
    if (lane < 3) {
        xout[warp * 3 + lane] = x[warp * 3 + lane];
    }
}

extern "C" void kernel_launch(void* const* d_in, const int* in_sizes, int n_in,
                              void* d_out, int out_size)
{
    const float* h   = (const float*)d_in[0];
    const float* x   = (const float*)d_in[1];
    const float* We1 = (const float*)d_in[2];
    const float* be1 = (const float*)d_in[3];
    const float* We2 = (const float*)d_in[4];
    const float* be2 = (const float*)d_in[5];
    const float* Wa  = (const float*)d_in[6];
    const float* ba  = (const float*)d_in[7];
    const float* Wn1 = (const float*)d_in[8];
    const float* bn1 = (const float*)d_in[9];
    const float* Wn2 = (const float*)d_in[10];
    const float* bn2 = (const float*)d_in[11];

    const int R = in_sizes[0] / 32;          // B*N rows
    float* out  = (float*)d_out;             // [R, 32]
    float* xout = out + (size_t)R * 32;      // [R, 3] passthrough

    const int threads = 256;                 // 8 warps = 8 rows per block
    const int blocks  = (R * 32 + threads - 1) / threads;
    egnn_diag_kernel<<<blocks, threads>>>(h, x, We1, be1, We2, be2, Wa, ba,
                                          Wn1, bn1, Wn2, bn2, out, xout, R);
}

// round 2
// speedup vs baseline: 1.2362x; 1.2362x over previous
#include <cuda_runtime.h>
#include <math.h>

// EGNN layer collapsed to the diagonal (eye-mask kills off-diagonal edges):
//   t1  = silu( h_r @ (We1[0:F]+We1[F:2F]) + sqrt(EPS)*We1[2F] + be1 )
//   t2  = silu( t1 @ We2 + be2 )
//   att = sigmoid( t2 @ Wa + ba );  he = att * t2
//   t3  = silu( h_r @ Wn1[0:F] + he @ Wn1[F:2F] + bn1 )
//   out = t3 @ Wn2 + bn2
// One warp per row, lane = neuron. Latency-bound kernel, so:
//  - 4 accumulators per layer (break FFMA chain)
//  - We2/Wn2 preloaded into registers (removes mem stalls on critical path)
//  - biases + x passthrough hoisted to the top

#define SQRT_EPS 0.0031622776601683794f  // sqrt(1e-5)
#define FULL 0xffffffffu

__device__ __forceinline__ float silu_f(float v) {
    return v / (1.0f + __expf(-v));
}

__global__ void __launch_bounds__(256)
egnn_diag_kernel(const float* __restrict__ h,
                 const float* __restrict__ x,
                 const float* __restrict__ We1, const float* __restrict__ be1,
                 const float* __restrict__ We2, const float* __restrict__ be2,
                 const float* __restrict__ Wa,  const float* __restrict__ ba,
                 const float* __restrict__ Wn1, const float* __restrict__ bn1,
                 const float* __restrict__ Wn2, const float* __restrict__ bn2,
                 float* __restrict__ out, float* __restrict__ xout, int R)
{
    const int warp = (blockIdx.x * blockDim.x + threadIdx.x) >> 5;
    const int lane = threadIdx.x & 31;
    if (warp >= R) return;

    // ---- independent work first: issue all of it before the serial chain ----
    const float hv = h[warp * 32 + lane];

    // x passthrough (3 floats per row)
    if (lane < 3) xout[warp * 3 + lane] = x[warp * 3 + lane];

    // biases (folding sqrt(EPS)*We1[2F] into b1)
    const float b1  = be1[lane] + SQRT_EPS * We1[64 * 32 + lane];
    const float b2  = be2[lane];
    const float wa  = Wa[lane];
    const float ba0 = ba[0];
    const float b3  = bn1[lane];
    const float b4  = bn2[lane];

    // Preload the weights that sit on the activation-dependent critical path
    // (layers 2 and 4) into registers — their loads are activation-independent
    // so they overlap with layer-1 compute.
    float we2r[32], wn2r[32];
    #pragma unroll
    for (int f = 0; f < 32; ++f) we2r[f] = We2[f * 32 + lane];
    #pragma unroll
    for (int f = 0; f < 32; ++f) wn2r[f] = Wn2[f * 32 + lane];

    // ---- layer 1: e_in = [h, h, sqrt(EPS)] @ We1 + be1 (streamed weights) ----
    float a0 = b1, a1 = 0.f, a2 = 0.f, a3 = 0.f;
    #pragma unroll
    for (int f = 0; f < 32; f += 4) {
        a0 += __shfl_sync(FULL, hv, f + 0) * (We1[(f + 0) * 32 + lane] + We1[(32 + f + 0) * 32 + lane]);
        a1 += __shfl_sync(FULL, hv, f + 1) * (We1[(f + 1) * 32 + lane] + We1[(32 + f + 1) * 32 + lane]);
        a2 += __shfl_sync(FULL, hv, f + 2) * (We1[(f + 2) * 32 + lane] + We1[(32 + f + 2) * 32 + lane]);
        a3 += __shfl_sync(FULL, hv, f + 3) * (We1[(f + 3) * 32 + lane] + We1[(32 + f + 3) * 32 + lane]);
    }
    const float t1 = silu_f((a0 + a1) + (a2 + a3));

    // ---- layer 2: t1 @ We2 + be2 (register weights) ----
    a0 = b2; a1 = 0.f; a2 = 0.f; a3 = 0.f;
    #pragma unroll
    for (int f = 0; f < 32; f += 4) {
        a0 += __shfl_sync(FULL, t1, f + 0) * we2r[f + 0];
        a1 += __shfl_sync(FULL, t1, f + 1) * we2r[f + 1];
        a2 += __shfl_sync(FULL, t1, f + 2) * we2r[f + 2];
        a3 += __shfl_sync(FULL, t1, f + 3) * we2r[f + 3];
    }
    const float t2 = silu_f((a0 + a1) + (a2 + a3));

    // ---- attention gate: sigmoid(t2 . Wa + ba) ----
    float s = t2 * wa;
    #pragma unroll
    for (int off = 16; off > 0; off >>= 1)
        s += __shfl_xor_sync(FULL, s, off);
    const float att = 1.0f / (1.0f + __expf(-(s + ba0)));
    const float he = att * t2;

    // ---- layer 3: [h, he] @ Wn1 + bn1 (streamed weights) ----
    a0 = b3; a1 = 0.f; a2 = 0.f; a3 = 0.f;
    #pragma unroll
    for (int f = 0; f < 32; f += 4) {
        a0 += __shfl_sync(FULL, hv, f + 0) * Wn1[(f + 0) * 32 + lane]
            + __shfl_sync(FULL, he, f + 0) * Wn1[(32 + f + 0) * 32 + lane];
        a1 += __shfl_sync(FULL, hv, f + 1) * Wn1[(f + 1) * 32 + lane]
            + __shfl_sync(FULL, he, f + 1) * Wn1[(32 + f + 1) * 32 + lane];
        a2 += __shfl_sync(FULL, hv, f + 2) * Wn1[(f + 2) * 32 + lane]
            + __shfl_sync(FULL, he, f + 2) * Wn1[(32 + f + 2) * 32 + lane];
        a3 += __shfl_sync(FULL, hv, f + 3) * Wn1[(f + 3) * 32 + lane]
            + __shfl_sync(FULL, he, f + 3) * Wn1[(32 + f + 3) * 32 + lane];
    }
    const float t3 = silu_f((a0 + a1) + (a2 + a3));

    // ---- layer 4: t3 @ Wn2 + bn2 (register weights) ----
    a0 = b4; a1 = 0.f; a2 = 0.f; a3 = 0.f;
    #pragma unroll
    for (int f = 0; f < 32; f += 4) {
        a0 += __shfl_sync(FULL, t3, f + 0) * wn2r[f + 0];
        a1 += __shfl_sync(FULL, t3, f + 1) * wn2r[f + 1];
        a2 += __shfl_sync(FULL, t3, f + 2) * wn2r[f + 2];
        a3 += __shfl_sync(FULL, t3, f + 3) * wn2r[f + 3];
    }

    out[warp * 32 + lane] = (a0 + a1) + (a2 + a3);
}

extern "C" void kernel_launch(void* const* d_in, const int* in_sizes, int n_in,
                              void* d_out, int out_size)
{
    const float* h   = (const float*)d_in[0];
    const float* x   = (const float*)d_in[1];
    const float* We1 = (const float*)d_in[2];
    const float* be1 = (const float*)d_in[3];
    const float* We2 = (const float*)d_in[4];
    const float* be2 = (const float*)d_in[5];
    const float* Wa  = (const float*)d_in[6];
    const float* ba  = (const float*)d_in[7];
    const float* Wn1 = (const float*)d_in[8];
    const float* bn1 = (const float*)d_in[9];
    const float* Wn2 = (const float*)d_in[10];
    const float* bn2 = (const float*)d_in[11];

    const int R = in_sizes[0] / 32;          // B*N rows
    float* out  = (float*)d_out;             // [R, 32]
    float* xout = out + (size_t)R * 32;      // [R, 3] passthrough

    const int threads = 256;                 // 8 warps = 8 rows per block
    const int blocks  = (R * 32 + threads - 1) / threads;
    egnn_diag_kernel<<<blocks, threads>>>(h, x, We1, be1, We2, be2, Wa, ba,
                                          Wn1, bn1, Wn2, bn2, out, xout, R);
}